// round 9
// baseline (speedup 1.0000x reference)
#include <cuda_runtime.h>
#include <cuda_fp16.h>
#include <cstdint>

#define NN   8192
#define FIN  512
#define FOUT 256

// ---- scratch (static device memory; no allocation) ----
__device__ __align__(16) float g_h [NN * FOUT];          // fp32 h
__device__ __align__(16) __half g_hT[FOUT * NN];         // fp16 h transposed [n][j]
__device__ __align__(16) float g_s1r[NN];
__device__ __align__(16) float g_s2r[NN];
__device__ __align__(16) float2 g_e1[NN];                // (exp(s1-m), exp(.2 s1-m))
__device__ __align__(16) float2 g_e2[NN];                // (exp(s2), exp(.2 s2))
__device__ __align__(16) uint32_t g_mask[NN * 256];      // bit-packed adj
__device__ __align__(16) float g_dpart[2 * NN * FOUT];
__device__ __align__(16) float g_z[2 * NN];

// ============================================================
// helpers
// ============================================================
__device__ __forceinline__ uint32_t smem_u32(const void* p) {
    uint32_t a;
    asm("{ .reg .u64 t; cvta.to.shared.u64 t, %1; cvt.u32.u64 %0, t; }" : "=r"(a) : "l"(p));
    return a;
}
__device__ __forceinline__ unsigned long long pack2(float lo, float hi) {
    unsigned long long r;
    asm("mov.b64 %0, {%1, %2};" : "=l"(r) : "f"(lo), "f"(hi));
    return r;
}
__device__ __forceinline__ void unpack2(unsigned long long v, float& lo, float& hi) {
    asm("mov.b64 {%0, %1}, %2;" : "=f"(lo), "=f"(hi) : "l"(v));
}
__device__ __forceinline__ uint32_t f16x2_pack(float hi, float lo) {
    uint32_t r;
    asm("cvt.rn.f16x2.f32 %0, %1, %2;" : "=r"(r) : "f"(hi), "f"(lo));
    return r;
}

// ============================================================
// Kernel 0: bit-pack adjacency
// ============================================================
__global__ __launch_bounds__(256) void pack_kernel(const int* __restrict__ adj,
                                                   uint32_t* __restrict__ mask)
{
    const int row = blockIdx.x;
    const int wid = threadIdx.x >> 5, lane = threadIdx.x & 31;
    const int* ar = adj + (size_t)row * NN;
#pragma unroll 4
    for (int i = 0; i < 32; i++) {
        int t = wid * 32 + i;
        int v = ar[t * 32 + lane];
        uint32_t b = __ballot_sync(0xffffffffu, v > 0);
        if (lane == 0) mask[row * 256 + t] = b;
    }
}

// ============================================================
// Kernel 1: h = input @ W, fp32 via packed fma.rn.f32x2
// ============================================================
#define G1_BM 128
#define G1_BN 128
#define G1_BK 16

__global__ __launch_bounds__(256) void gemm_h_kernel(
    const float* __restrict__ A, const float* __restrict__ B, float* __restrict__ C)
{
    __shared__ float As[G1_BK][G1_BM + 4];
    __shared__ float Bs[G1_BK][G1_BN + 4];

    const int row0 = blockIdx.x * G1_BM;
    const int col0 = blockIdx.y * G1_BN;
    const int tid = threadIdx.x;
    const int tx = tid & 15, ty = tid >> 4;

    unsigned long long acc2[8][4];
#pragma unroll
    for (int i = 0; i < 8; i++)
#pragma unroll
        for (int j = 0; j < 4; j++) acc2[i][j] = 0ULL;

    for (int k0 = 0; k0 < FIN; k0 += G1_BK) {
#pragma unroll
        for (int it = 0; it < 2; it++) {
            int i = tid + it * 256;
            int r = i >> 2, c4 = i & 3;
            float4 v = *(const float4*)&A[(row0 + r) * FIN + k0 + c4 * 4];
            As[c4 * 4 + 0][r] = v.x;
            As[c4 * 4 + 1][r] = v.y;
            As[c4 * 4 + 2][r] = v.z;
            As[c4 * 4 + 3][r] = v.w;
        }
#pragma unroll
        for (int it = 0; it < 2; it++) {
            int i = tid + it * 256;
            int r = i >> 5, c4 = i & 31;
            float4 v = *(const float4*)&B[(k0 + r) * FOUT + col0 + c4 * 4];
            *(float4*)&Bs[r][c4 * 4] = v;
        }
        __syncthreads();

#pragma unroll
        for (int k = 0; k < G1_BK; k++) {
            float4 a0 = *(const float4*)&As[k][ty * 8];
            float4 a1 = *(const float4*)&As[k][ty * 8 + 4];
            float af[8] = {a0.x, a0.y, a0.z, a0.w, a1.x, a1.y, a1.z, a1.w};
            ulonglong2 b01 = ((const ulonglong2*)&Bs[k][tx * 8])[0];
            ulonglong2 b23 = ((const ulonglong2*)&Bs[k][tx * 8])[1];
            unsigned long long bb[4] = {b01.x, b01.y, b23.x, b23.y};
#pragma unroll
            for (int i = 0; i < 8; i++) {
                unsigned long long pa = pack2(af[i], af[i]);
#pragma unroll
                for (int j = 0; j < 4; j++)
                    asm("fma.rn.f32x2 %0, %1, %2, %0;"
                        : "+l"(acc2[i][j]) : "l"(pa), "l"(bb[j]));
            }
        }
        __syncthreads();
    }

#pragma unroll
    for (int i = 0; i < 8; i++) {
        int r = row0 + ty * 8 + i;
#pragma unroll
        for (int j4 = 0; j4 < 2; j4++) {
            float v0, v1, v2, v3;
            unpack2(acc2[i][j4 * 2 + 0], v0, v1);
            unpack2(acc2[i][j4 * 2 + 1], v2, v3);
            *(float4*)&C[r * FOUT + col0 + tx * 8 + j4 * 4] = make_float4(v0, v1, v2, v3);
        }
    }
}

// ============================================================
// Kernel 1b: transpose+convert h fp32 [NN][FOUT] -> hT fp16 [FOUT][NN]
// ============================================================
__global__ __launch_bounds__(256) void t_kernel(const float* __restrict__ h,
                                                __half* __restrict__ hT)
{
    __shared__ __half tile[32][33];
    const int r0 = blockIdx.x * 32, c0 = blockIdx.y * 32;
    const int lane = threadIdx.x & 31, w = threadIdx.x >> 5;
#pragma unroll
    for (int ii = 0; ii < 4; ii++) {
        int r = w * 4 + ii;
        tile[r][lane] = __float2half(h[(size_t)(r0 + r) * FOUT + c0 + lane]);
    }
    __syncthreads();
#pragma unroll
    for (int ii = 0; ii < 4; ii++) {
        int c = w * 4 + ii;
        hT[(size_t)(c0 + c) * NN + r0 + lane] = tile[lane][c];
    }
}

// ============================================================
// Kernel 2: s1/s2 dot products (raw)
// ============================================================
__global__ __launch_bounds__(256) void s_kernel(
    const float* __restrict__ h, const float* __restrict__ a)
{
    int row = blockIdx.x * 8 + (threadIdx.x >> 5);
    int lane = threadIdx.x & 31;
    float a1 = 0.f, a2 = 0.f;
#pragma unroll
    for (int c = lane; c < FOUT; c += 32) {
        float hv = h[row * FOUT + c];
        a1 = fmaf(hv, a[c], a1);
        a2 = fmaf(hv, a[FOUT + c], a2);
    }
#pragma unroll
    for (int o = 16; o; o >>= 1) {
        a1 += __shfl_xor_sync(0xffffffffu, a1, o);
        a2 += __shfl_xor_sync(0xffffffffu, a2, o);
    }
    if (lane == 0) { g_s1r[row] = a1; g_s2r[row] = a2; }
}

// ============================================================
// Kernel 2b: S2MAX reduction + factor tables (1 block)
// ============================================================
__global__ __launch_bounds__(256) void prep_kernel(void)
{
    __shared__ float red[256];
    float mx = -3.0e38f;
    for (int i = threadIdx.x; i < NN; i += 256) mx = fmaxf(mx, g_s2r[i]);
    red[threadIdx.x] = mx;
    __syncthreads();
#pragma unroll
    for (int s = 128; s; s >>= 1) {
        if (threadIdx.x < s) red[threadIdx.x] = fmaxf(red[threadIdx.x], red[threadIdx.x + s]);
        __syncthreads();
    }
    const float S2MAX = red[0];
    for (int r = threadIdx.x; r < NN; r += 256) {
        float s1 = g_s1r[r], s2 = g_s2r[r];
        float x = s1 + S2MAX;
        float m = fmaxf(x, 0.2f * x);
        g_e1[r] = make_float2(expf(s1 - m), expf(0.2f * s1 - m));
        g_e2[r] = make_float2(expf(s2), expf(0.2f * s2));
    }
}

// ============================================================
// Kernel 3: fused attention GEMM, mma.sync fp16 m16n8k16.
//   512 threads / 16 warps: 8 row-groups (32 rows each) x 2 n-groups (9 nb).
//   grid 128 = 32 rowtiles(256) x 2 kh x 2 nh.
// ============================================================
#define AT_THREADS 512
#define KT 32
#define ATILES 128
#define HSTRH 40                         // halves per Hs row
#define HS_BYTES (136 * HSTRH * 2)       // 10880
#define OFF_HS0 0
#define OFF_HS1 HS_BYTES
#define OFF_E2  (2 * HS_BYTES)
#define AT_SMEM (OFF_E2 + 4096 * 8)

__global__ void __launch_bounds__(AT_THREADS, 1) attn_kernel(void)
{
    extern __shared__ char dsm[];
    __half* HsB[2] = { (__half*)(dsm + OFF_HS0), (__half*)(dsm + OFF_HS1) };
    float2* e2sm = (float2*)(dsm + OFF_E2);

    const int tid = threadIdx.x, wid = tid >> 5, lane = tid & 31;
    const int q = lane >> 2, tc = lane & 3;
    const int wr = wid & 7, wc = wid >> 3;
    const int nbo = wc * 8;                      // nb blocks: wc0 -> 0..8, wc1 -> 8..16
    const int rt = blockIdx.x >> 2, kh = (blockIdx.x >> 1) & 1, nh = blockIdx.x & 1;
    const int row0 = rt * 256, kbase = kh * 4096, nbase = nh * 128;

    // ---- stage e2 table (32 KB) ----
    {
        uint32_t dst = smem_u32(e2sm) + (uint32_t)tid * 16u;
        const float4* src = (const float4*)(g_e2 + kbase) + tid;
#pragma unroll
        for (int it = 0; it < 4; it++)
            asm volatile("cp.async.cg.shared.global [%0], [%1], 16;"
                         :: "r"(dst + it * 8192u), "l"(src + it * 512));
        asm volatile("cp.async.commit_group;");
    }
    // ---- ones rows (n local 128..135), both buffers ----
    if (tid < 128) {
        int r = 128 + (tid >> 4), c = tid & 15;
        ((uint32_t*)HsB[0])[(r * HSTRH) / 2 + c] = 0x3C003C00u;
        ((uint32_t*)HsB[1])[(r * HSTRH) / 2 + c] = 0x3C003C00u;
    }
    // ---- prefetch H tile 0 ----
    {
        uint32_t dstb = smem_u32(HsB[0]);
        const __half* src = g_hT + (size_t)nbase * NN + kbase;
        int n = tid >> 2, c16 = tid & 3;
        asm volatile("cp.async.cg.shared.global [%0], [%1], 16;"
                     :: "r"(dstb + (uint32_t)(n * HSTRH * 2 + c16 * 16)),
                        "l"(src + (size_t)n * NN + c16 * 8));
        asm volatile("cp.async.commit_group;");
    }

    // ---- per-row constants (rows q + {0,8,16,24} of warp's 32) ----
    float f1p[4], f1n[4];
    const uint32_t* mbase = g_mask + (size_t)(row0 + wr * 32 + q) * 256 + kh * 128;
#pragma unroll
    for (int r = 0; r < 4; r++) {
        float2 e = g_e1[row0 + wr * 32 + q + r * 8];
        f1p[r] = e.x; f1n[r] = e.y;
    }
    uint32_t mcur[4];
#pragma unroll
    for (int r = 0; r < 4; r++) mcur[r] = mbase[r * 8 * 256];

    float acc[2][9][4];
#pragma unroll
    for (int g = 0; g < 2; g++)
#pragma unroll
        for (int nb = 0; nb < 9; nb++)
#pragma unroll
            for (int j = 0; j < 4; j++) acc[g][nb][j] = 0.f;

    for (int t = 0; t < ATILES; t++) {
        if (t + 1 < ATILES) {
            uint32_t dstb = smem_u32(HsB[(t + 1) & 1]);
            const __half* src = g_hT + (size_t)nbase * NN + kbase + (t + 1) * KT;
            int n = tid >> 2, c16 = tid & 3;
            asm volatile("cp.async.cg.shared.global [%0], [%1], 16;"
                         :: "r"(dstb + (uint32_t)(n * HSTRH * 2 + c16 * 16)),
                            "l"(src + (size_t)n * NN + c16 * 8));
            asm volatile("cp.async.commit_group;");
            asm volatile("cp.async.wait_group 1;");
        } else {
            asm volatile("cp.async.wait_group 0;");
        }
        __syncthreads();

        uint32_t mnext[4] = {0, 0, 0, 0};
        if (t + 1 < ATILES) {
#pragma unroll
            for (int r = 0; r < 4; r++) mnext[r] = mbase[(t + 1) + r * 8 * 256];
        }

        const __half* Hb = HsB[t & 1];
        const int kl0 = t * KT;

#pragma unroll
        for (int c = 0; c < 2; c++) {
            const int kc = c * 16 + 2 * tc;
            float2 e0 = e2sm[kl0 + kc];
            float2 e1 = e2sm[kl0 + kc + 1];
            float2 e8 = e2sm[kl0 + kc + 8];
            float2 e9 = e2sm[kl0 + kc + 9];
            const uint32_t b0m = 1u << kc, b1m = 2u << kc;
            const uint32_t b8m = 256u << kc, b9m = 512u << kc;

            uint32_t af[2][4];
#pragma unroll
            for (int r = 0; r < 4; r++) {
                float p0 = fmaxf(f1p[r] * e0.x, f1n[r] * e0.y);
                float p1 = fmaxf(f1p[r] * e1.x, f1n[r] * e1.y);
                float p8 = fmaxf(f1p[r] * e8.x, f1n[r] * e8.y);
                float p9 = fmaxf(f1p[r] * e9.x, f1n[r] * e9.y);
                p0 = (mcur[r] & b0m) ? p0 : 0.f;
                p1 = (mcur[r] & b1m) ? p1 : 0.f;
                p8 = (mcur[r] & b8m) ? p8 : 0.f;
                p9 = (mcur[r] & b9m) ? p9 : 0.f;
                af[r >> 1][(r & 1)]     = f16x2_pack(p1, p0);
                af[r >> 1][(r & 1) + 2] = f16x2_pack(p9, p8);
            }

            const __half* bp = Hb + q * HSTRH + c * 16 + 2 * tc;
#pragma unroll
            for (int nb = 0; nb < 9; nb++) {
                int nbi = nbo + nb;
                uint32_t b0 = *(const uint32_t*)(bp + nbi * 8 * HSTRH);
                uint32_t b1 = *(const uint32_t*)(bp + nbi * 8 * HSTRH + 8);
                asm volatile(
                    "mma.sync.aligned.m16n8k16.row.col.f32.f16.f16.f32 "
                    "{%0,%1,%2,%3}, {%4,%5,%6,%7}, {%8,%9}, {%0,%1,%2,%3};"
                    : "+f"(acc[0][nb][0]), "+f"(acc[0][nb][1]),
                      "+f"(acc[0][nb][2]), "+f"(acc[0][nb][3])
                    : "r"(af[0][0]), "r"(af[0][1]), "r"(af[0][2]), "r"(af[0][3]),
                      "r"(b0), "r"(b1));
                asm volatile(
                    "mma.sync.aligned.m16n8k16.row.col.f32.f16.f16.f32 "
                    "{%0,%1,%2,%3}, {%4,%5,%6,%7}, {%8,%9}, {%0,%1,%2,%3};"
                    : "+f"(acc[1][nb][0]), "+f"(acc[1][nb][1]),
                      "+f"(acc[1][nb][2]), "+f"(acc[1][nb][3])
                    : "r"(af[1][0]), "r"(af[1][1]), "r"(af[1][2]), "r"(af[1][3]),
                      "r"(b0), "r"(b1));
            }
        }
        __syncthreads();

#pragma unroll
        for (int r = 0; r < 4; r++) mcur[r] = mnext[r];
    }

    // ---- store partial D + z ----
    float* dp = g_dpart + (size_t)kh * NN * FOUT;
#pragma unroll
    for (int g = 0; g < 2; g++) {
        const int rlo = row0 + wr * 32 + g * 16 + q;
        const int rhi = rlo + 8;
#pragma unroll
        for (int nb = 0; nb < 9; nb++) {
            int nbi = nbo + nb;
            if (nbi < 16) {
                int c = nbase + nbi * 8 + tc * 2;
                *(float2*)&dp[(size_t)rlo * FOUT + c] = make_float2(acc[g][nb][0], acc[g][nb][1]);
                *(float2*)&dp[(size_t)rhi * FOUT + c] = make_float2(acc[g][nb][2], acc[g][nb][3]);
            }
        }
        if (wc == 1 && nh == 0 && tc == 0) {
            g_z[kh * NN + rlo] = acc[g][8][0];
            g_z[kh * NN + rhi] = acc[g][8][2];
        }
    }
}

// ============================================================
// Kernel 4: combine K-split partials, normalize, ELU
// ============================================================
__global__ __launch_bounds__(256) void combine_kernel(float* __restrict__ out)
{
    int idx = blockIdx.x * 256 + threadIdx.x;
    const float4* d0 = (const float4*)g_dpart;
    const float4* d1 = d0 + (NN * FOUT / 4);
    float4 a = d0[idx], b = d1[idx];
    int row = idx >> 6;
    float inv = 1.0f / (g_z[row] + g_z[NN + row]);
    float4 o; float t;
    t = (a.x + b.x) * inv; o.x = (t > 0.f) ? t : expm1f(t);
    t = (a.y + b.y) * inv; o.y = (t > 0.f) ? t : expm1f(t);
    t = (a.z + b.z) * inv; o.z = (t > 0.f) ? t : expm1f(t);
    t = (a.w + b.w) * inv; o.w = (t > 0.f) ? t : expm1f(t);
    ((float4*)out)[idx] = o;
}

// ============================================================
// launch
// ============================================================
extern "C" void kernel_launch(void* const* d_in, const int* in_sizes, int n_in,
                              void* d_out, int out_size)
{
    const float* input = (const float*)d_in[0];   // [8192, 512]
    const int*   adj   = (const int*)  d_in[1];   // [8192, 8192]
    const float* W     = (const float*)d_in[2];   // [512, 256]
    const float* a     = (const float*)d_in[3];   // [512, 1]
    float* out = (float*)d_out;                   // [8192, 256]

    float* h;
    __half* hT;
    uint32_t* mask;
    cudaGetSymbolAddress((void**)&h, g_h);
    cudaGetSymbolAddress((void**)&hT, g_hT);
    cudaGetSymbolAddress((void**)&mask, g_mask);

    cudaFuncSetAttribute(attn_kernel, cudaFuncAttributeMaxDynamicSharedMemorySize, AT_SMEM);

    gemm_h_kernel<<<dim3(NN / G1_BM, FOUT / G1_BN), 256>>>(input, W, h);
    s_kernel<<<NN / 8, 256>>>(h, a);
    prep_kernel<<<1, 256>>>();
    t_kernel<<<dim3(NN / 32, FOUT / 32), 256>>>(h, hT);
    pack_kernel<<<NN, 256>>>(adj, mask);
    attn_kernel<<<128, AT_THREADS, AT_SMEM>>>();
    combine_kernel<<<NN * FOUT / 4 / 256, 256>>>(out);
}

// round 11
// speedup vs baseline: 1.0203x; 1.0203x over previous
#include <cuda_runtime.h>
#include <cuda_fp16.h>
#include <cstdint>

#define NN   8192
#define FIN  512
#define FOUT 256

// ---- scratch (static device memory; no allocation) ----
__device__ __align__(16) float g_h [NN * FOUT];          // fp32 h
__device__ __align__(16) __half g_hT[FOUT * NN];         // fp16 h transposed [n][j]
__device__ __align__(16) float g_s1r[NN];
__device__ __align__(16) float g_s2r[NN];
__device__ __align__(16) float2 g_e1[NN];                // (exp(s1-m), exp(.2 s1-m))
__device__ __align__(16) float2 g_e2[NN];                // (exp(s2), exp(.2 s2))
__device__ __align__(16) uint32_t g_mask[NN * 256];      // bit-packed adj
__device__ __align__(16) float g_dpart[2 * NN * FOUT];
__device__ __align__(16) float g_z[2 * NN];

// ============================================================
// helpers
// ============================================================
__device__ __forceinline__ uint32_t smem_u32(const void* p) {
    uint32_t a;
    asm("{ .reg .u64 t; cvta.to.shared.u64 t, %1; cvt.u32.u64 %0, t; }" : "=r"(a) : "l"(p));
    return a;
}
__device__ __forceinline__ unsigned long long pack2(float lo, float hi) {
    unsigned long long r;
    asm("mov.b64 %0, {%1, %2};" : "=l"(r) : "f"(lo), "f"(hi));
    return r;
}
__device__ __forceinline__ void unpack2(unsigned long long v, float& lo, float& hi) {
    asm("mov.b64 {%0, %1}, %2;" : "=f"(lo), "=f"(hi) : "l"(v));
}
__device__ __forceinline__ uint32_t f16x2_pack(float hi, float lo) {
    uint32_t r;
    asm("cvt.rn.f16x2.f32 %0, %1, %2;" : "=r"(r) : "f"(hi), "f"(lo));
    return r;
}

// ============================================================
// Kernel 0: bit-pack adjacency
// ============================================================
__global__ __launch_bounds__(256) void pack_kernel(const int* __restrict__ adj,
                                                   uint32_t* __restrict__ mask)
{
    const int row = blockIdx.x;
    const int wid = threadIdx.x >> 5, lane = threadIdx.x & 31;
    const int* ar = adj + (size_t)row * NN;
#pragma unroll 4
    for (int i = 0; i < 32; i++) {
        int t = wid * 32 + i;
        int v = ar[t * 32 + lane];
        uint32_t b = __ballot_sync(0xffffffffu, v > 0);
        if (lane == 0) mask[row * 256 + t] = b;
    }
}

// ============================================================
// Kernel 1: h = input @ W, fp32 via packed fma.rn.f32x2
// ============================================================
#define G1_BM 128
#define G1_BN 128
#define G1_BK 16

__global__ __launch_bounds__(256) void gemm_h_kernel(
    const float* __restrict__ A, const float* __restrict__ B, float* __restrict__ C)
{
    __shared__ float As[G1_BK][G1_BM + 4];
    __shared__ float Bs[G1_BK][G1_BN + 4];

    const int row0 = blockIdx.x * G1_BM;
    const int col0 = blockIdx.y * G1_BN;
    const int tid = threadIdx.x;
    const int tx = tid & 15, ty = tid >> 4;

    unsigned long long acc2[8][4];
#pragma unroll
    for (int i = 0; i < 8; i++)
#pragma unroll
        for (int j = 0; j < 4; j++) acc2[i][j] = 0ULL;

    for (int k0 = 0; k0 < FIN; k0 += G1_BK) {
#pragma unroll
        for (int it = 0; it < 2; it++) {
            int i = tid + it * 256;
            int r = i >> 2, c4 = i & 3;
            float4 v = *(const float4*)&A[(row0 + r) * FIN + k0 + c4 * 4];
            As[c4 * 4 + 0][r] = v.x;
            As[c4 * 4 + 1][r] = v.y;
            As[c4 * 4 + 2][r] = v.z;
            As[c4 * 4 + 3][r] = v.w;
        }
#pragma unroll
        for (int it = 0; it < 2; it++) {
            int i = tid + it * 256;
            int r = i >> 5, c4 = i & 31;
            float4 v = *(const float4*)&B[(k0 + r) * FOUT + col0 + c4 * 4];
            *(float4*)&Bs[r][c4 * 4] = v;
        }
        __syncthreads();

#pragma unroll
        for (int k = 0; k < G1_BK; k++) {
            float4 a0 = *(const float4*)&As[k][ty * 8];
            float4 a1 = *(const float4*)&As[k][ty * 8 + 4];
            float af[8] = {a0.x, a0.y, a0.z, a0.w, a1.x, a1.y, a1.z, a1.w};
            ulonglong2 b01 = ((const ulonglong2*)&Bs[k][tx * 8])[0];
            ulonglong2 b23 = ((const ulonglong2*)&Bs[k][tx * 8])[1];
            unsigned long long bb[4] = {b01.x, b01.y, b23.x, b23.y};
#pragma unroll
            for (int i = 0; i < 8; i++) {
                unsigned long long pa = pack2(af[i], af[i]);
#pragma unroll
                for (int j = 0; j < 4; j++)
                    asm("fma.rn.f32x2 %0, %1, %2, %0;"
                        : "+l"(acc2[i][j]) : "l"(pa), "l"(bb[j]));
            }
        }
        __syncthreads();
    }

#pragma unroll
    for (int i = 0; i < 8; i++) {
        int r = row0 + ty * 8 + i;
#pragma unroll
        for (int j4 = 0; j4 < 2; j4++) {
            float v0, v1, v2, v3;
            unpack2(acc2[i][j4 * 2 + 0], v0, v1);
            unpack2(acc2[i][j4 * 2 + 1], v2, v3);
            *(float4*)&C[r * FOUT + col0 + tx * 8 + j4 * 4] = make_float4(v0, v1, v2, v3);
        }
    }
}

// ============================================================
// Kernel 1b: transpose+convert h fp32 [NN][FOUT] -> hT fp16 [FOUT][NN]
// ============================================================
__global__ __launch_bounds__(256) void t_kernel(const float* __restrict__ h,
                                                __half* __restrict__ hT)
{
    __shared__ __half tile[32][33];
    const int r0 = blockIdx.x * 32, c0 = blockIdx.y * 32;
    const int lane = threadIdx.x & 31, w = threadIdx.x >> 5;
#pragma unroll
    for (int ii = 0; ii < 4; ii++) {
        int r = w * 4 + ii;
        tile[r][lane] = __float2half(h[(size_t)(r0 + r) * FOUT + c0 + lane]);
    }
    __syncthreads();
#pragma unroll
    for (int ii = 0; ii < 4; ii++) {
        int c = w * 4 + ii;
        hT[(size_t)(c0 + c) * NN + r0 + lane] = tile[lane][c];
    }
}

// ============================================================
// Kernel 2: s1/s2 dot products (raw)
// ============================================================
__global__ __launch_bounds__(256) void s_kernel(
    const float* __restrict__ h, const float* __restrict__ a)
{
    int row = blockIdx.x * 8 + (threadIdx.x >> 5);
    int lane = threadIdx.x & 31;
    float a1 = 0.f, a2 = 0.f;
#pragma unroll
    for (int c = lane; c < FOUT; c += 32) {
        float hv = h[row * FOUT + c];
        a1 = fmaf(hv, a[c], a1);
        a2 = fmaf(hv, a[FOUT + c], a2);
    }
#pragma unroll
    for (int o = 16; o; o >>= 1) {
        a1 += __shfl_xor_sync(0xffffffffu, a1, o);
        a2 += __shfl_xor_sync(0xffffffffu, a2, o);
    }
    if (lane == 0) { g_s1r[row] = a1; g_s2r[row] = a2; }
}

// ============================================================
// Kernel 2b: S2MAX reduction + factor tables (1 block)
// ============================================================
__global__ __launch_bounds__(256) void prep_kernel(void)
{
    __shared__ float red[256];
    float mx = -3.0e38f;
    for (int i = threadIdx.x; i < NN; i += 256) mx = fmaxf(mx, g_s2r[i]);
    red[threadIdx.x] = mx;
    __syncthreads();
#pragma unroll
    for (int s = 128; s; s >>= 1) {
        if (threadIdx.x < s) red[threadIdx.x] = fmaxf(red[threadIdx.x], red[threadIdx.x + s]);
        __syncthreads();
    }
    const float S2MAX = red[0];
    for (int r = threadIdx.x; r < NN; r += 256) {
        float s1 = g_s1r[r], s2 = g_s2r[r];
        float x = s1 + S2MAX;
        float m = fmaxf(x, 0.2f * x);
        g_e1[r] = make_float2(expf(s1 - m), expf(0.2f * s1 - m));
        g_e2[r] = make_float2(expf(s2), expf(0.2f * s2));
    }
}

// ============================================================
// Kernel 3: fused attention GEMM, mma.sync fp16 m16n8k16.
//   2 CTAs/SM: 256 threads, 8 warps x 16 rows, 128-row tiles.
//   grid 256 = 64 rowtiles(128) x 2 kh x 2 nh.  All CTAs resident.
// ============================================================
#define AT_THREADS 256
#define KT 32
#define ATILES 128
#define HSTRH 40                         // halves per Hs row
#define HS_BYTES (136 * HSTRH * 2)       // 10880
#define OFF_HS0 0
#define OFF_HS1 HS_BYTES
#define OFF_E2  (2 * HS_BYTES)
#define AT_SMEM (OFF_E2 + 4096 * 8)      // 54528 B -> 2 CTAs = 109 KB/SM

__global__ void __launch_bounds__(AT_THREADS, 2) attn_kernel(void)
{
    extern __shared__ char dsm[];
    __half* HsB[2] = { (__half*)(dsm + OFF_HS0), (__half*)(dsm + OFF_HS1) };
    float2* e2sm = (float2*)(dsm + OFF_E2);

    const int tid = threadIdx.x, wid = tid >> 5, lane = tid & 31;
    const int q = lane >> 2, tc = lane & 3;
    const int rt = blockIdx.x >> 2, kh = (blockIdx.x >> 1) & 1, nh = blockIdx.x & 1;
    const int row0 = rt * 128, kbase = kh * 4096, nbase = nh * 128;

    // ---- stage e2 table (32 KB) ----
    {
        uint32_t dst = smem_u32(e2sm) + (uint32_t)tid * 16u;
        const float4* src = (const float4*)(g_e2 + kbase) + tid;
#pragma unroll
        for (int it = 0; it < 8; it++)
            asm volatile("cp.async.cg.shared.global [%0], [%1], 16;"
                         :: "r"(dst + it * 4096u), "l"(src + it * 256));
        asm volatile("cp.async.commit_group;");
    }
    // ---- ones rows (n local 128..135), both buffers ----
    for (int i = tid; i < 8 * HSTRH / 2; i += AT_THREADS) {
        int r = 128 + i / (HSTRH / 2), c = i % (HSTRH / 2);
        ((uint32_t*)HsB[0])[(r * HSTRH) / 2 + c] = 0x3C003C00u;
        ((uint32_t*)HsB[1])[(r * HSTRH) / 2 + c] = 0x3C003C00u;
    }
    // ---- prefetch H tile 0: 128 n-rows x 32 halves ----
    {
        uint32_t dstb = smem_u32(HsB[0]);
        const __half* src = g_hT + (size_t)nbase * NN + kbase;
#pragma unroll
        for (int it = 0; it < 2; it++) {
            int i = tid + it * AT_THREADS;
            int n = i >> 2, c16 = i & 3;
            asm volatile("cp.async.cg.shared.global [%0], [%1], 16;"
                         :: "r"(dstb + (uint32_t)(n * HSTRH * 2 + c16 * 16)),
                            "l"(src + (size_t)n * NN + c16 * 8));
        }
        asm volatile("cp.async.commit_group;");
    }

    // ---- per-row constants (rows q, q+8 of warp's 16) ----
    float f1p[2], f1n[2];
    const uint32_t* mrow[2];
#pragma unroll
    for (int r = 0; r < 2; r++) {
        int grow = row0 + wid * 16 + q + r * 8;
        float2 e = g_e1[grow];
        f1p[r] = e.x; f1n[r] = e.y;
        mrow[r] = g_mask + (size_t)grow * 256 + kh * 128;
    }
    uint32_t mcur[2];
#pragma unroll
    for (int r = 0; r < 2; r++) mcur[r] = mrow[r][0];

    float acc[17][4];
#pragma unroll
    for (int nb = 0; nb < 17; nb++)
#pragma unroll
        for (int j = 0; j < 4; j++) acc[nb][j] = 0.f;

    for (int t = 0; t < ATILES; t++) {
        if (t + 1 < ATILES) {
            uint32_t dstb = smem_u32(HsB[(t + 1) & 1]);
            const __half* src = g_hT + (size_t)nbase * NN + kbase + (t + 1) * KT;
#pragma unroll
            for (int it = 0; it < 2; it++) {
                int i = tid + it * AT_THREADS;
                int n = i >> 2, c16 = i & 3;
                asm volatile("cp.async.cg.shared.global [%0], [%1], 16;"
                             :: "r"(dstb + (uint32_t)(n * HSTRH * 2 + c16 * 16)),
                                "l"(src + (size_t)n * NN + c16 * 8));
            }
            asm volatile("cp.async.commit_group;");
            asm volatile("cp.async.wait_group 1;");
        } else {
            asm volatile("cp.async.wait_group 0;");
        }
        __syncthreads();

        uint32_t mnext[2] = {0, 0};
        if (t + 1 < ATILES) {
#pragma unroll
            for (int r = 0; r < 2; r++) mnext[r] = mrow[r][t + 1];
        }

        const __half* Hb = HsB[t & 1];
        const int kl0 = t * KT;

#pragma unroll
        for (int c = 0; c < 2; c++) {           // two k16 chunks
            const int kc = c * 16 + 2 * tc;
            float2 e0 = e2sm[kl0 + kc];
            float2 e1 = e2sm[kl0 + kc + 1];
            float2 e8 = e2sm[kl0 + kc + 8];
            float2 e9 = e2sm[kl0 + kc + 9];
            const uint32_t b0m = 1u << kc, b1m = 2u << kc;
            const uint32_t b8m = 256u << kc, b9m = 512u << kc;

            uint32_t af[4];
#pragma unroll
            for (int r = 0; r < 2; r++) {
                float p0 = fmaxf(f1p[r] * e0.x, f1n[r] * e0.y);
                float p1 = fmaxf(f1p[r] * e1.x, f1n[r] * e1.y);
                float p8 = fmaxf(f1p[r] * e8.x, f1n[r] * e8.y);
                float p9 = fmaxf(f1p[r] * e9.x, f1n[r] * e9.y);
                p0 = (mcur[r] & b0m) ? p0 : 0.f;
                p1 = (mcur[r] & b1m) ? p1 : 0.f;
                p8 = (mcur[r] & b8m) ? p8 : 0.f;
                p9 = (mcur[r] & b9m) ? p9 : 0.f;
                af[r]     = f16x2_pack(p1, p0);   // row q(+8r), k lo pair
                af[r + 2] = f16x2_pack(p9, p8);   // row q(+8r), k hi pair
            }

            const __half* bp = Hb + q * HSTRH + c * 16 + 2 * tc;
#pragma unroll
            for (int nb = 0; nb < 17; nb++) {
                uint32_t b0 = *(const uint32_t*)(bp + nb * 8 * HSTRH);
                uint32_t b1 = *(const uint32_t*)(bp + nb * 8 * HSTRH + 8);
                asm volatile(
                    "mma.sync.aligned.m16n8k16.row.col.f32.f16.f16.f32 "
                    "{%0,%1,%2,%3}, {%4,%5,%6,%7}, {%8,%9}, {%0,%1,%2,%3};"
                    : "+f"(acc[nb][0]), "+f"(acc[nb][1]),
                      "+f"(acc[nb][2]), "+f"(acc[nb][3])
                    : "r"(af[0]), "r"(af[1]), "r"(af[2]), "r"(af[3]),
                      "r"(b0), "r"(b1));
            }
        }
        __syncthreads();

#pragma unroll
        for (int r = 0; r < 2; r++) mcur[r] = mnext[r];
    }

    // ---- store partial D + z ----
    float* dp = g_dpart + (size_t)kh * NN * FOUT;
    {
        const int rlo = row0 + wid * 16 + q;
        const int rhi = rlo + 8;
#pragma unroll
        for (int nb = 0; nb < 16; nb++) {
            int c = nbase + nb * 8 + tc * 2;
            *(float2*)&dp[(size_t)rlo * FOUT + c] = make_float2(acc[nb][0], acc[nb][1]);
            *(float2*)&dp[(size_t)rhi * FOUT + c] = make_float2(acc[nb][2], acc[nb][3]);
        }
        if (nh == 0 && tc == 0) {
            g_z[kh * NN + rlo] = acc[16][0];
            g_z[kh * NN + rhi] = acc[16][2];
        }
    }
}

// ============================================================
// Kernel 4: combine K-split partials, normalize, ELU
// ============================================================
__global__ __launch_bounds__(256) void combine_kernel(float* __restrict__ out)
{
    int idx = blockIdx.x * 256 + threadIdx.x;
    const float4* d0 = (const float4*)g_dpart;
    const float4* d1 = d0 + (NN * FOUT / 4);
    float4 a = d0[idx], b = d1[idx];
    int row = idx >> 6;
    float inv = 1.0f / (g_z[row] + g_z[NN + row]);
    float4 o; float t;
    t = (a.x + b.x) * inv; o.x = (t > 0.f) ? t : expm1f(t);
    t = (a.y + b.y) * inv; o.y = (t > 0.f) ? t : expm1f(t);
    t = (a.z + b.z) * inv; o.z = (t > 0.f) ? t : expm1f(t);
    t = (a.w + b.w) * inv; o.w = (t > 0.f) ? t : expm1f(t);
    ((float4*)out)[idx] = o;
}

// ============================================================
// launch
// ============================================================
extern "C" void kernel_launch(void* const* d_in, const int* in_sizes, int n_in,
                              void* d_out, int out_size)
{
    const float* input = (const float*)d_in[0];   // [8192, 512]
    const int*   adj   = (const int*)  d_in[1];   // [8192, 8192]
    const float* W     = (const float*)d_in[2];   // [512, 256]
    const float* a     = (const float*)d_in[3];   // [512, 1]
    float* out = (float*)d_out;                   // [8192, 256]

    float* h;
    __half* hT;
    uint32_t* mask;
    cudaGetSymbolAddress((void**)&h, g_h);
    cudaGetSymbolAddress((void**)&hT, g_hT);
    cudaGetSymbolAddress((void**)&mask, g_mask);

    cudaFuncSetAttribute(attn_kernel, cudaFuncAttributeMaxDynamicSharedMemorySize, AT_SMEM);

    gemm_h_kernel<<<dim3(NN / G1_BM, FOUT / G1_BN), 256>>>(input, W, h);
    s_kernel<<<NN / 8, 256>>>(h, a);
    prep_kernel<<<1, 256>>>();
    t_kernel<<<dim3(NN / 32, FOUT / 32), 256>>>(h, hT);
    pack_kernel<<<NN, 256>>>(adj, mask);
    attn_kernel<<<256, AT_THREADS, AT_SMEM>>>();
    combine_kernel<<<NN * FOUT / 4 / 256, 256>>>(out);
}